// round 5
// baseline (speedup 1.0000x reference)
#include <cuda_runtime.h>
#include <cstdint>

#define F 128
#define MAXN 100000
#define MAXE 1600000
#define SCAN_B 1024
#define MAXBLK ((MAXN + SCAN_B - 1) / SCAN_B)   // 98

// Scratch (allocation-free: __device__ globals, referenced directly by kernels)
__device__ __align__(16) float g_bufA[(size_t)MAXN * F];   // 51.2 MB
__device__ __align__(16) float g_bufB[(size_t)MAXN * F];   // 51.2 MB
__device__ int   g_cntIn[MAXN];
__device__ int   g_cntOut[MAXN];
__device__ int   g_excl[MAXN];
__device__ int   g_bsum[MAXBLK];
__device__ int   g_off[MAXN];
__device__ int   g_cursor[MAXN];
__device__ int   g_eidx[MAXE];
__device__ float g_dinvOut[MAXN];
__device__ float g_dinvIn[MAXN];

// ---------------------------------------------------------------------------
__global__ void zero_cnt_kernel(int n) {
    int i = blockIdx.x * blockDim.x + threadIdx.x;
    if (i < n) { g_cntIn[i] = 0; g_cntOut[i] = 0; }
}

__global__ void hist_kernel(const int* __restrict__ src,
                            const int* __restrict__ dst, int nE) {
    int i = blockIdx.x * blockDim.x + threadIdx.x;
    if (i < nE) {
        atomicAdd(&g_cntOut[src[i]], 1);
        atomicAdd(&g_cntIn[dst[i]], 1);
    }
}

// Per-block inclusive scan (Hillis-Steele) -> exclusive within block + block sum
__global__ void scan_block_kernel(int n) {
    __shared__ int s[SCAN_B];
    int tid = threadIdx.x;
    int i = blockIdx.x * SCAN_B + tid;
    int v = (i < n) ? g_cntIn[i] : 0;
    s[tid] = v;
    __syncthreads();
#pragma unroll
    for (int o = 1; o < SCAN_B; o <<= 1) {
        int t = (tid >= o) ? s[tid - o] : 0;
        __syncthreads();
        s[tid] += t;
        __syncthreads();
    }
    if (i < n) g_excl[i] = s[tid] - v;
    if (tid == SCAN_B - 1) g_bsum[blockIdx.x] = s[tid];
}

// Exclusive scan of block sums (nb <= 128), one block of 128 threads
__global__ void scan_small_kernel(int nb) {
    __shared__ int s[128];
    int tid = threadIdx.x;
    int v = (tid < nb) ? g_bsum[tid] : 0;
    s[tid] = v;
    __syncthreads();
#pragma unroll
    for (int o = 1; o < 128; o <<= 1) {
        int t = (tid >= o) ? s[tid - o] : 0;
        __syncthreads();
        s[tid] += t;
        __syncthreads();
    }
    if (tid < nb) g_bsum[tid] = s[tid] - v;
}

__global__ void finalize_kernel(int n) {
    int i = blockIdx.x * blockDim.x + threadIdx.x;
    if (i < n) {
        int o = g_excl[i] + g_bsum[i / SCAN_B];
        g_off[i] = o;
        g_cursor[i] = o;
        g_dinvIn[i]  = rsqrtf(fmaxf((float)g_cntIn[i],  1.f));
        g_dinvOut[i] = rsqrtf(fmaxf((float)g_cntOut[i], 1.f));
    }
}

__global__ void fill_kernel(const int* __restrict__ src,
                            const int* __restrict__ dst, int nE) {
    int i = blockIdx.x * blockDim.x + threadIdx.x;
    if (i < nE) {
        int d = dst[i];
        int pos = atomicAdd(&g_cursor[d], 1);
        g_eidx[pos] = src[i];
    }
}

// ---------------------------------------------------------------------------
// GEMM: g_bufA[64 rows x 128 cols per block] = Xt @ W  (static 48KB smem)
//   mode 0: X = Xin,    xt[i][k] = X[i][k] * dinvOut[i]
//   mode 1: X = g_bufB, xt[i][k] = relu(X[i][k]*dinvIn[i] + bias[k]) * dinvOut[i]
__global__ __launch_bounds__(256)
void gemm_kernel(const float* __restrict__ Xin, const float* __restrict__ W,
                 const float* __restrict__ bias, int nN, int mode) {
    __shared__ __align__(16) float sX[64][F];   // 32 KB
    __shared__ __align__(16) float sW[32][F];   // 16 KB
    const int tid = threadIdx.x;
    const int row0 = blockIdx.x * 64;
    const float* X = (mode == 0) ? Xin : g_bufB;

    // Load + transform X tile: 64 rows * 32 float4 = 2048 float4; 8 per thread
#pragma unroll
    for (int j = 0; j < 8; j++) {
        int f4i = j * 256 + tid;
        int r   = f4i >> 5;
        int k4  = f4i & 31;
        int grow = row0 + r;
        float4 v = make_float4(0.f, 0.f, 0.f, 0.f);
        if (grow < nN) {
            v = ((const float4*)(X + (size_t)grow * F))[k4];
            float da = g_dinvOut[grow];
            if (mode == 1) {
                float db = g_dinvIn[grow];
                float4 bb = ((const float4*)bias)[k4];
                v.x = fmaxf(fmaf(v.x, db, bb.x), 0.f);
                v.y = fmaxf(fmaf(v.y, db, bb.y), 0.f);
                v.z = fmaxf(fmaf(v.z, db, bb.z), 0.f);
                v.w = fmaxf(fmaf(v.w, db, bb.w), 0.f);
            }
            v.x *= da; v.y *= da; v.z *= da; v.w *= da;
        }
        *(float4*)&sX[r][k4 * 4] = v;
    }
    __syncthreads();

    const int tx = tid & 31;   // cols tx*4 .. tx*4+3
    const int ty = tid >> 5;   // rows ty*8 .. ty*8+7
    float4 acc[8];
#pragma unroll
    for (int r = 0; r < 8; r++) acc[r] = make_float4(0.f, 0.f, 0.f, 0.f);

    for (int kc = 0; kc < 4; kc++) {
        // Stage W rows [kc*32, kc*32+32): 1024 float4, 4 per thread
        const float4* Wg = (const float4*)(W + (size_t)kc * 32 * F);
#pragma unroll
        for (int i = 0; i < 4; i++)
            ((float4*)&sW[0][0])[i * 256 + tid] = Wg[i * 256 + tid];
        __syncthreads();

#pragma unroll
        for (int kk4 = 0; kk4 < 8; kk4++) {
            float4 xr[8];
#pragma unroll
            for (int r = 0; r < 8; r++)
                xr[r] = *(const float4*)&sX[ty * 8 + r][kc * 32 + kk4 * 4];
#pragma unroll
            for (int j = 0; j < 4; j++) {
                float4 w = *(const float4*)&sW[kk4 * 4 + j][tx * 4];
#pragma unroll
                for (int r = 0; r < 8; r++) {
                    const float* xp = (const float*)&xr[r];
                    float xs = xp[j];
                    acc[r].x = fmaf(xs, w.x, acc[r].x);
                    acc[r].y = fmaf(xs, w.y, acc[r].y);
                    acc[r].z = fmaf(xs, w.z, acc[r].z);
                    acc[r].w = fmaf(xs, w.w, acc[r].w);
                }
            }
        }
        __syncthreads();
    }

#pragma unroll
    for (int r = 0; r < 8; r++) {
        int grow = row0 + ty * 8 + r;
        if (grow < nN)
            *(float4*)(g_bufA + (size_t)grow * F + tx * 4) = acc[r];
    }
}

// ---------------------------------------------------------------------------
// Gather-aggregate (atomic-free): one warp per dst node, lane owns a float4.
// g_bufB[d][:] = sum over CSR in-edges of g_bufA[src][:]
__global__ void gather_agg_kernel(int nN) {
    int node = blockIdx.x * (blockDim.x >> 5) + (threadIdx.x >> 5);
    int lane = threadIdx.x & 31;
    if (node >= nN) return;
    int b = g_off[node];
    int e = b + g_cntIn[node];
    float4 acc = make_float4(0.f, 0.f, 0.f, 0.f);
    for (int j = b; j < e; j++) {
        int s = g_eidx[j];   // warp-uniform -> broadcast
        float4 v = ((const float4*)(g_bufA + (size_t)s * F))[lane];
        acc.x += v.x; acc.y += v.y; acc.z += v.z; acc.w += v.w;
    }
    ((float4*)(g_bufB + (size_t)node * F))[lane] = acc;
}

// ---------------------------------------------------------------------------
// Classifier: out[i][c] = sum_k relu(g_bufB[i][k]*dinvIn[i]+b2[k]) * Wc[k][c] + bc[c]
__global__ void classifier_kernel(const float* __restrict__ b2,
                                  const float* __restrict__ Wc,
                                  const float* __restrict__ bc,
                                  float* __restrict__ out, int nN) {
    int gw = (blockIdx.x * blockDim.x + threadIdx.x) >> 5;
    int lane = threadIdx.x & 31;
    if (gw >= nN) return;
    float db = g_dinvIn[gw];
    float4 v = ((const float4*)(g_bufB + (size_t)gw * F))[lane];
    float4 bb = ((const float4*)b2)[lane];
    float h[4];
    h[0] = fmaxf(fmaf(v.x, db, bb.x), 0.f);
    h[1] = fmaxf(fmaf(v.y, db, bb.y), 0.f);
    h[2] = fmaxf(fmaf(v.z, db, bb.z), 0.f);
    h[3] = fmaxf(fmaf(v.w, db, bb.w), 0.f);

    float a0 = 0.f, a1 = 0.f, a2 = 0.f, a3 = 0.f;
    const float4* Wc4 = (const float4*)Wc;
#pragma unroll
    for (int j = 0; j < 4; j++) {
        float4 w = Wc4[lane * 4 + j];
        a0 = fmaf(h[j], w.x, a0);
        a1 = fmaf(h[j], w.y, a1);
        a2 = fmaf(h[j], w.z, a2);
        a3 = fmaf(h[j], w.w, a3);
    }
#pragma unroll
    for (int o = 16; o > 0; o >>= 1) {
        a0 += __shfl_xor_sync(0xffffffffu, a0, o);
        a1 += __shfl_xor_sync(0xffffffffu, a1, o);
        a2 += __shfl_xor_sync(0xffffffffu, a2, o);
        a3 += __shfl_xor_sync(0xffffffffu, a3, o);
    }
    if (lane == 0)
        ((float4*)out)[gw] = make_float4(a0 + bc[0], a1 + bc[1], a2 + bc[2], a3 + bc[3]);
}

// ---------------------------------------------------------------------------
extern "C" void kernel_launch(void* const* d_in, const int* in_sizes, int n_in,
                              void* d_out, int out_size) {
    const float* features = (const float*)d_in[0];
    const int*   src      = (const int*)d_in[1];   // JAX default x64-disabled -> int32
    const int*   dst      = (const int*)d_in[2];
    const float* W1       = (const float*)d_in[3];
    const float* b1       = (const float*)d_in[4];
    const float* W2       = (const float*)d_in[5];
    const float* b2       = (const float*)d_in[6];
    const float* Wc       = (const float*)d_in[7];
    const float* bc       = (const float*)d_in[8];
    float*       out      = (float*)d_out;

    const int nN = in_sizes[0] / F;
    const int nE = in_sizes[1];
    const int nb = (nN + SCAN_B - 1) / SCAN_B;

    // CSR build + degrees (int atomics only)
    zero_cnt_kernel<<<(nN + 255) / 256, 256>>>(nN);
    hist_kernel<<<(nE + 255) / 256, 256>>>(src, dst, nE);
    scan_block_kernel<<<nb, SCAN_B>>>(nN);
    scan_small_kernel<<<1, 128>>>(nb);
    finalize_kernel<<<(nN + 255) / 256, 256>>>(nN);
    fill_kernel<<<(nE + 255) / 256, 256>>>(src, dst, nE);

    // layer 1: scale+GEMM -> bufA; gather bufA -> bufB
    gemm_kernel<<<(nN + 63) / 64, 256>>>(features, W1, b1, nN, 0);
    gather_agg_kernel<<<(nN + 7) / 8, 256>>>(nN);

    // layer 2: relu/bias/scale fused GEMM (bufB) -> bufA; gather -> bufB
    gemm_kernel<<<(nN + 63) / 64, 256>>>(features, W2, b1, nN, 1);
    gather_agg_kernel<<<(nN + 7) / 8, 256>>>(nN);

    // classifier (bufB -> out)
    classifier_kernel<<<(nN * 32 + 255) / 256, 256>>>(b2, Wc, bc, out, nN);
}

// round 6
// speedup vs baseline: 1.1362x; 1.1362x over previous
#include <cuda_runtime.h>
#include <cuda_bf16.h>
#include <cstdint>

#define F 128
#define MAXN 100000
#define MAXE 1600000
#define SCAN_B 1024
#define MAXBLK ((MAXN + SCAN_B - 1) / SCAN_B)   // 98

// Scratch (allocation-free: __device__ globals, referenced directly by kernels)
__device__ __align__(16) float g_bufA[(size_t)MAXN * F];   // 51.2 MB
__device__ __align__(16) float g_bufB[(size_t)MAXN * F];   // 51.2 MB
__device__ int   g_cntIn[MAXN];
__device__ int   g_cntOut[MAXN];
__device__ int   g_excl[MAXN];
__device__ int   g_bsum[MAXBLK];
__device__ int   g_off[MAXN];
__device__ int   g_cursor[MAXN];
__device__ int   g_eidx[MAXE];
__device__ float g_dinvOut[MAXN];
__device__ float g_dinvIn[MAXN];

// ---------------------------------------------------------------------------
__global__ void zero_cnt_kernel(int n) {
    int i = blockIdx.x * blockDim.x + threadIdx.x;
    if (i < n) { g_cntIn[i] = 0; g_cntOut[i] = 0; }
}

__global__ void hist_kernel(const int* __restrict__ src,
                            const int* __restrict__ dst, int nE) {
    int i = blockIdx.x * blockDim.x + threadIdx.x;
    if (i < nE) {
        atomicAdd(&g_cntOut[src[i]], 1);
        atomicAdd(&g_cntIn[dst[i]], 1);
    }
}

__global__ void scan_block_kernel(int n) {
    __shared__ int s[SCAN_B];
    int tid = threadIdx.x;
    int i = blockIdx.x * SCAN_B + tid;
    int v = (i < n) ? g_cntIn[i] : 0;
    s[tid] = v;
    __syncthreads();
#pragma unroll
    for (int o = 1; o < SCAN_B; o <<= 1) {
        int t = (tid >= o) ? s[tid - o] : 0;
        __syncthreads();
        s[tid] += t;
        __syncthreads();
    }
    if (i < n) g_excl[i] = s[tid] - v;
    if (tid == SCAN_B - 1) g_bsum[blockIdx.x] = s[tid];
}

__global__ void scan_small_kernel(int nb) {
    __shared__ int s[128];
    int tid = threadIdx.x;
    int v = (tid < nb) ? g_bsum[tid] : 0;
    s[tid] = v;
    __syncthreads();
#pragma unroll
    for (int o = 1; o < 128; o <<= 1) {
        int t = (tid >= o) ? s[tid - o] : 0;
        __syncthreads();
        s[tid] += t;
        __syncthreads();
    }
    if (tid < nb) g_bsum[tid] = s[tid] - v;
}

__global__ void finalize_kernel(int n) {
    int i = blockIdx.x * blockDim.x + threadIdx.x;
    if (i < n) {
        int o = g_excl[i] + g_bsum[i / SCAN_B];
        g_off[i] = o;
        g_cursor[i] = o;
        g_dinvIn[i]  = rsqrtf(fmaxf((float)g_cntIn[i],  1.f));
        g_dinvOut[i] = rsqrtf(fmaxf((float)g_cntOut[i], 1.f));
    }
}

__global__ void fill_kernel(const int* __restrict__ src,
                            const int* __restrict__ dst, int nE) {
    int i = blockIdx.x * blockDim.x + threadIdx.x;
    if (i < nE) {
        int d = dst[i];
        int pos = atomicAdd(&g_cursor[d], 1);
        g_eidx[pos] = src[i];
    }
}

// ---------------------------------------------------------------------------
// bf16x3 tensor-core GEMM: g_bufA[128 x 128 per block] = transform(X) @ W
//   mode 0: x = Xin[i][k]  * dinvOut[i]
//   mode 1: x = relu(g_bufB[i][k]*dinvIn[i] + bias[k]) * dinvOut[i]
// Each fp32 split into bf16 hi+lo; D += Ah*Bh + Ah*Bl + Al*Bh (fp32 acc).
#define XPITCH 40   // bf16 elements per smem row (conflict-free for frag pattern)

__device__ __forceinline__ void mma_bf16(float* d, const uint32_t* a,
                                         uint32_t b0, uint32_t b1) {
    asm volatile(
        "mma.sync.aligned.m16n8k16.row.col.f32.bf16.bf16.f32 "
        "{%0,%1,%2,%3}, {%4,%5,%6,%7}, {%8,%9}, {%0,%1,%2,%3};"
        : "+f"(d[0]), "+f"(d[1]), "+f"(d[2]), "+f"(d[3])
        : "r"(a[0]), "r"(a[1]), "r"(a[2]), "r"(a[3]), "r"(b0), "r"(b1));
}

__device__ __forceinline__ void split_bf16(float v, unsigned short& h, unsigned short& l) {
    __nv_bfloat16 hb = __float2bfloat16(v);
    __nv_bfloat16 lb = __float2bfloat16(v - __bfloat162float(hb));
    h = __bfloat16_as_ushort(hb);
    l = __bfloat16_as_ushort(lb);
}

__global__ __launch_bounds__(256, 2)
void gemm_mma_kernel(const float* __restrict__ Xin, const float* __restrict__ W,
                     const float* __restrict__ bias, int nN, int mode) {
    __shared__ __align__(16) unsigned short sXhi[128][XPITCH];
    __shared__ __align__(16) unsigned short sXlo[128][XPITCH];
    __shared__ __align__(16) unsigned short sWhi[128][XPITCH];  // [n][k] (transposed)
    __shared__ __align__(16) unsigned short sWlo[128][XPITCH];

    const int tid  = threadIdx.x;
    const int wid  = tid >> 5;
    const int lane = tid & 31;
    const int g    = lane >> 2;     // group 0..7
    const int tig  = lane & 3;      // thread-in-group 0..3
    const int row0 = blockIdx.x * 128;
    const int wm   = wid & 3;       // warp row tile: rows wm*32 .. +31
    const int wn   = wid >> 2;      // warp col tile: cols wn*64 .. +63
    const float* X = (mode == 0) ? Xin : (const float*)g_bufB;

    float acc[2][8][4];
#pragma unroll
    for (int mt = 0; mt < 2; mt++)
#pragma unroll
        for (int nt = 0; nt < 8; nt++)
#pragma unroll
            for (int q = 0; q < 4; q++) acc[mt][nt][q] = 0.f;

    for (int kc = 0; kc < 4; kc++) {
        // ---- stage X chunk [128 rows x 32 k] with transform + hi/lo split ----
#pragma unroll
        for (int p = 0; p < 4; p++) {
            int idx = p * 256 + tid;        // 0..1023
            int r   = idx >> 3;
            int c4  = idx & 7;              // float4 within chunk
            int grow = row0 + r;
            float4 v = make_float4(0.f, 0.f, 0.f, 0.f);
            if (grow < nN) {
                v = *(const float4*)(X + (size_t)grow * F + kc * 32 + c4 * 4);
                float da = g_dinvOut[grow];
                if (mode == 1) {
                    float db = g_dinvIn[grow];
                    float4 bb = ((const float4*)bias)[kc * 8 + c4];
                    v.x = fmaxf(fmaf(v.x, db, bb.x), 0.f);
                    v.y = fmaxf(fmaf(v.y, db, bb.y), 0.f);
                    v.z = fmaxf(fmaf(v.z, db, bb.z), 0.f);
                    v.w = fmaxf(fmaf(v.w, db, bb.w), 0.f);
                }
                v.x *= da; v.y *= da; v.z *= da; v.w *= da;
            }
            unsigned short h0, l0, h1, l1, h2, l2, h3, l3;
            split_bf16(v.x, h0, l0); split_bf16(v.y, h1, l1);
            split_bf16(v.z, h2, l2); split_bf16(v.w, h3, l3);
            int c = c4 * 4;
            *(uint32_t*)&sXhi[r][c]     = (uint32_t)h0 | ((uint32_t)h1 << 16);
            *(uint32_t*)&sXhi[r][c + 2] = (uint32_t)h2 | ((uint32_t)h3 << 16);
            *(uint32_t*)&sXlo[r][c]     = (uint32_t)l0 | ((uint32_t)l1 << 16);
            *(uint32_t*)&sXlo[r][c + 2] = (uint32_t)l2 | ((uint32_t)l3 << 16);
        }
        // ---- stage W chunk [32 k x 128 n] transposed into [n][k] ----
#pragma unroll
        for (int p = 0; p < 2; p++) {
            int t  = p * 256 + tid;         // 0..511
            int kp = t & 15;                // k pair index
            int ng = t >> 4;                // n group (4 cols)
            int k0 = kc * 32 + 2 * kp;
            float4 r0 = ((const float4*)(W + (size_t)k0 * F))[ng];
            float4 r1 = ((const float4*)(W + (size_t)(k0 + 1) * F))[ng];
            const float* a0 = (const float*)&r0;
            const float* a1 = (const float*)&r1;
#pragma unroll
            for (int i = 0; i < 4; i++) {
                int n = ng * 4 + i;
                unsigned short ha, la, hb, lb;
                split_bf16(a0[i], ha, la);
                split_bf16(a1[i], hb, lb);
                *(uint32_t*)&sWhi[n][2 * kp] = (uint32_t)ha | ((uint32_t)hb << 16);
                *(uint32_t*)&sWlo[n][2 * kp] = (uint32_t)la | ((uint32_t)lb << 16);
            }
        }
        __syncthreads();

        // ---- compute: 2 k16 steps per chunk ----
#pragma unroll
        for (int ks = 0; ks < 2; ks++) {
            int kb = ks * 16;
            uint32_t ah[2][4], al[2][4];
#pragma unroll
            for (int mt = 0; mt < 2; mt++) {
                int r1 = wm * 32 + mt * 16 + g;
                ah[mt][0] = *(const uint32_t*)&sXhi[r1][kb + 2 * tig];
                ah[mt][1] = *(const uint32_t*)&sXhi[r1 + 8][kb + 2 * tig];
                ah[mt][2] = *(const uint32_t*)&sXhi[r1][kb + 8 + 2 * tig];
                ah[mt][3] = *(const uint32_t*)&sXhi[r1 + 8][kb + 8 + 2 * tig];
                al[mt][0] = *(const uint32_t*)&sXlo[r1][kb + 2 * tig];
                al[mt][1] = *(const uint32_t*)&sXlo[r1 + 8][kb + 2 * tig];
                al[mt][2] = *(const uint32_t*)&sXlo[r1][kb + 8 + 2 * tig];
                al[mt][3] = *(const uint32_t*)&sXlo[r1 + 8][kb + 8 + 2 * tig];
            }
#pragma unroll
            for (int nt = 0; nt < 8; nt++) {
                int n = wn * 64 + nt * 8 + g;
                uint32_t bh0 = *(const uint32_t*)&sWhi[n][kb + 2 * tig];
                uint32_t bh1 = *(const uint32_t*)&sWhi[n][kb + 8 + 2 * tig];
                uint32_t bl0 = *(const uint32_t*)&sWlo[n][kb + 2 * tig];
                uint32_t bl1 = *(const uint32_t*)&sWlo[n][kb + 8 + 2 * tig];
#pragma unroll
                for (int mt = 0; mt < 2; mt++) {
                    mma_bf16(acc[mt][nt], ah[mt], bh0, bh1);  // hi*hi
                    mma_bf16(acc[mt][nt], ah[mt], bl0, bl1);  // hi*lo
                    mma_bf16(acc[mt][nt], al[mt], bh0, bh1);  // lo*hi
                }
            }
        }
        __syncthreads();
    }

    // ---- store D ----
#pragma unroll
    for (int mt = 0; mt < 2; mt++) {
#pragma unroll
        for (int nt = 0; nt < 8; nt++) {
            int col = wn * 64 + nt * 8 + 2 * tig;
            int r1 = row0 + wm * 32 + mt * 16 + g;
            if (r1 < nN)
                *(float2*)(g_bufA + (size_t)r1 * F + col) =
                    make_float2(acc[mt][nt][0], acc[mt][nt][1]);
            if (r1 + 8 < nN)
                *(float2*)(g_bufA + (size_t)(r1 + 8) * F + col) =
                    make_float2(acc[mt][nt][2], acc[mt][nt][3]);
        }
    }
}

// ---------------------------------------------------------------------------
// Gather-aggregate (atomic-free): one warp per dst node, lane owns a float4.
// Unrolled by 4 for MLP. g_bufB[d][:] = sum over CSR in-edges of g_bufA[s][:]
__global__ void gather_agg_kernel(int nN) {
    int node = blockIdx.x * (blockDim.x >> 5) + (threadIdx.x >> 5);
    int lane = threadIdx.x & 31;
    if (node >= nN) return;
    int b = g_off[node];
    int e = b + g_cntIn[node];
    float4 acc = make_float4(0.f, 0.f, 0.f, 0.f);
    int j = b;
    int e4 = b + ((e - b) & ~3);
    for (; j < e4; j += 4) {
        int s0 = g_eidx[j];
        int s1 = g_eidx[j + 1];
        int s2 = g_eidx[j + 2];
        int s3 = g_eidx[j + 3];
        float4 v0 = ((const float4*)(g_bufA + (size_t)s0 * F))[lane];
        float4 v1 = ((const float4*)(g_bufA + (size_t)s1 * F))[lane];
        float4 v2 = ((const float4*)(g_bufA + (size_t)s2 * F))[lane];
        float4 v3 = ((const float4*)(g_bufA + (size_t)s3 * F))[lane];
        acc.x += v0.x + v1.x + v2.x + v3.x;
        acc.y += v0.y + v1.y + v2.y + v3.y;
        acc.z += v0.z + v1.z + v2.z + v3.z;
        acc.w += v0.w + v1.w + v2.w + v3.w;
    }
    for (; j < e; j++) {
        int s = g_eidx[j];
        float4 v = ((const float4*)(g_bufA + (size_t)s * F))[lane];
        acc.x += v.x; acc.y += v.y; acc.z += v.z; acc.w += v.w;
    }
    ((float4*)(g_bufB + (size_t)node * F))[lane] = acc;
}

// ---------------------------------------------------------------------------
__global__ void classifier_kernel(const float* __restrict__ b2,
                                  const float* __restrict__ Wc,
                                  const float* __restrict__ bc,
                                  float* __restrict__ out, int nN) {
    int gw = (blockIdx.x * blockDim.x + threadIdx.x) >> 5;
    int lane = threadIdx.x & 31;
    if (gw >= nN) return;
    float db = g_dinvIn[gw];
    float4 v = ((const float4*)(g_bufB + (size_t)gw * F))[lane];
    float4 bb = ((const float4*)b2)[lane];
    float h[4];
    h[0] = fmaxf(fmaf(v.x, db, bb.x), 0.f);
    h[1] = fmaxf(fmaf(v.y, db, bb.y), 0.f);
    h[2] = fmaxf(fmaf(v.z, db, bb.z), 0.f);
    h[3] = fmaxf(fmaf(v.w, db, bb.w), 0.f);

    float a0 = 0.f, a1 = 0.f, a2 = 0.f, a3 = 0.f;
    const float4* Wc4 = (const float4*)Wc;
#pragma unroll
    for (int j = 0; j < 4; j++) {
        float4 w = Wc4[lane * 4 + j];
        a0 = fmaf(h[j], w.x, a0);
        a1 = fmaf(h[j], w.y, a1);
        a2 = fmaf(h[j], w.z, a2);
        a3 = fmaf(h[j], w.w, a3);
    }
#pragma unroll
    for (int o = 16; o > 0; o >>= 1) {
        a0 += __shfl_xor_sync(0xffffffffu, a0, o);
        a1 += __shfl_xor_sync(0xffffffffu, a1, o);
        a2 += __shfl_xor_sync(0xffffffffu, a2, o);
        a3 += __shfl_xor_sync(0xffffffffu, a3, o);
    }
    if (lane == 0)
        ((float4*)out)[gw] = make_float4(a0 + bc[0], a1 + bc[1], a2 + bc[2], a3 + bc[3]);
}

// ---------------------------------------------------------------------------
extern "C" void kernel_launch(void* const* d_in, const int* in_sizes, int n_in,
                              void* d_out, int out_size) {
    const float* features = (const float*)d_in[0];
    const int*   src      = (const int*)d_in[1];
    const int*   dst      = (const int*)d_in[2];
    const float* W1       = (const float*)d_in[3];
    const float* b1       = (const float*)d_in[4];
    const float* W2       = (const float*)d_in[5];
    const float* b2       = (const float*)d_in[6];
    const float* Wc       = (const float*)d_in[7];
    const float* bc       = (const float*)d_in[8];
    float*       out      = (float*)d_out;

    const int nN = in_sizes[0] / F;
    const int nE = in_sizes[1];
    const int nb = (nN + SCAN_B - 1) / SCAN_B;

    // CSR build + degrees (int atomics only)
    zero_cnt_kernel<<<(nN + 255) / 256, 256>>>(nN);
    hist_kernel<<<(nE + 255) / 256, 256>>>(src, dst, nE);
    scan_block_kernel<<<nb, SCAN_B>>>(nN);
    scan_small_kernel<<<1, 128>>>(nb);
    finalize_kernel<<<(nN + 255) / 256, 256>>>(nN);
    fill_kernel<<<(nE + 255) / 256, 256>>>(src, dst, nE);

    // layer 1: scale+GEMM (tensor) -> bufA; gather bufA -> bufB
    gemm_mma_kernel<<<(nN + 127) / 128, 256>>>(features, W1, b1, nN, 0);
    gather_agg_kernel<<<(nN + 7) / 8, 256>>>(nN);

    // layer 2: relu/bias/scale fused GEMM (bufB) -> bufA; gather -> bufB
    gemm_mma_kernel<<<(nN + 127) / 128, 256>>>(features, W2, b1, nN, 1);
    gather_agg_kernel<<<(nN + 7) / 8, 256>>>(nN);

    // classifier (bufB -> out)
    classifier_kernel<<<(nN * 32 + 255) / 256, 256>>>(b2, Wc, bc, out, nN);
}

// round 7
// speedup vs baseline: 1.2461x; 1.0967x over previous
#include <cuda_runtime.h>
#include <cuda_bf16.h>
#include <cstdint>

#define F 128
#define MAXN 100000
#define MAXNP 100096   // padded to multiple of 128 (GEMM tile)
#define MAXE 1600000
#define SCAN_B 1024
#define MAXBLK ((MAXN + SCAN_B - 1) / SCAN_B)   // 98

// Scratch (allocation-free: __device__ globals)
__device__ __align__(16) float    g_bufA[(size_t)MAXNP * F];       // 51.2 MB
__device__ __align__(16) uint32_t g_Xhi[(size_t)MAXNP * (F / 2)];  // 25.6 MB (bf16 pairs)
__device__ __align__(16) uint32_t g_Xlo[(size_t)MAXNP * (F / 2)];  // 25.6 MB
__device__ __align__(4) unsigned short g_W1hi[F * F];  // [n][k] transposed
__device__ __align__(4) unsigned short g_W1lo[F * F];
__device__ __align__(4) unsigned short g_W2hi[F * F];
__device__ __align__(4) unsigned short g_W2lo[F * F];
__device__ int   g_cntIn[MAXN];
__device__ int   g_cntOut[MAXN];
__device__ int   g_excl[MAXN];
__device__ int   g_bsum[MAXBLK];
__device__ int   g_off[MAXN];
__device__ int   g_cursor[MAXN];
__device__ int   g_eidx[MAXE];
__device__ float g_dinvOut[MAXN];
__device__ float g_dinvIn[MAXN];

__device__ __forceinline__ void split_bf16(float v, unsigned short& h, unsigned short& l) {
    __nv_bfloat16 hb = __float2bfloat16(v);
    __nv_bfloat16 lb = __float2bfloat16(v - __bfloat162float(hb));
    h = __bfloat16_as_ushort(hb);
    l = __bfloat16_as_ushort(lb);
}

// ---------------------------------------------------------------------------
__global__ void zero_cnt_kernel(int n) {
    int i = blockIdx.x * blockDim.x + threadIdx.x;
    if (i < n) { g_cntIn[i] = 0; g_cntOut[i] = 0; }
}

__global__ void hist_kernel(const int* __restrict__ src,
                            const int* __restrict__ dst, int nE) {
    int i = blockIdx.x * blockDim.x + threadIdx.x;
    if (i < nE) {
        atomicAdd(&g_cntOut[src[i]], 1);
        atomicAdd(&g_cntIn[dst[i]], 1);
    }
}

__global__ void dinv_kernel(int n) {
    int i = blockIdx.x * blockDim.x + threadIdx.x;
    if (i < n) {
        g_dinvIn[i]  = rsqrtf(fmaxf((float)g_cntIn[i],  1.f));
        g_dinvOut[i] = rsqrtf(fmaxf((float)g_cntOut[i], 1.f));
    }
}

__global__ void scan_block_kernel(int n) {
    __shared__ int s[SCAN_B];
    int tid = threadIdx.x;
    int i = blockIdx.x * SCAN_B + tid;
    int v = (i < n) ? g_cntIn[i] : 0;
    s[tid] = v;
    __syncthreads();
#pragma unroll
    for (int o = 1; o < SCAN_B; o <<= 1) {
        int t = (tid >= o) ? s[tid - o] : 0;
        __syncthreads();
        s[tid] += t;
        __syncthreads();
    }
    if (i < n) g_excl[i] = s[tid] - v;
    if (tid == SCAN_B - 1) g_bsum[blockIdx.x] = s[tid];
}

__global__ void scan_small_kernel(int nb) {
    __shared__ int s[128];
    int tid = threadIdx.x;
    int v = (tid < nb) ? g_bsum[tid] : 0;
    s[tid] = v;
    __syncthreads();
#pragma unroll
    for (int o = 1; o < 128; o <<= 1) {
        int t = (tid >= o) ? s[tid - o] : 0;
        __syncthreads();
        s[tid] += t;
        __syncthreads();
    }
    if (tid < nb) g_bsum[tid] = s[tid] - v;
}

__global__ void offsets_kernel(int n) {
    int i = blockIdx.x * blockDim.x + threadIdx.x;
    if (i < n) {
        int o = g_excl[i] + g_bsum[i / SCAN_B];
        g_off[i] = o;
        g_cursor[i] = o;
    }
}

__global__ void fill_kernel(const int* __restrict__ src,
                            const int* __restrict__ dst, int nE) {
    int i = blockIdx.x * blockDim.x + threadIdx.x;
    if (i < nE) {
        int d = dst[i];
        int pos = atomicAdd(&g_cursor[d], 1);
        g_eidx[pos] = src[i];
    }
}

// ---------------------------------------------------------------------------
// Pre-split both weight matrices, transposed to [n][k]
__global__ void wsplit_kernel(const float* __restrict__ W1,
                              const float* __restrict__ W2) {
    int t = blockIdx.x * blockDim.x + threadIdx.x;   // 0..32767
    int which = t >> 14;
    int i = t & 16383;
    int k = i >> 7, n = i & 127;
    unsigned short h, l;
    if (which == 0) {
        split_bf16(W1[i], h, l);
        g_W1hi[n * F + k] = h; g_W1lo[n * F + k] = l;
    } else {
        split_bf16(W2[i], h, l);
        g_W2hi[n * F + k] = h; g_W2lo[n * F + k] = l;
    }
}

// features * dinvOut -> split bf16 hi/lo (layer-1 GEMM input)
__global__ void prep_kernel(const float* __restrict__ feat, int nN) {
    int i = blockIdx.x * blockDim.x + threadIdx.x;   // one float4 each
    if (i >= nN * 32) return;
    int row = i >> 5, c4 = i & 31;
    float4 v = ((const float4*)feat)[i];
    float da = g_dinvOut[row];
    v.x *= da; v.y *= da; v.z *= da; v.w *= da;
    unsigned short h0, l0, h1, l1, h2, l2, h3, l3;
    split_bf16(v.x, h0, l0); split_bf16(v.y, h1, l1);
    split_bf16(v.z, h2, l2); split_bf16(v.w, h3, l3);
    size_t w = (size_t)row * 64 + c4 * 2;
    g_Xhi[w]     = (uint32_t)h0 | ((uint32_t)h1 << 16);
    g_Xhi[w + 1] = (uint32_t)h2 | ((uint32_t)h3 << 16);
    g_Xlo[w]     = (uint32_t)l0 | ((uint32_t)l1 << 16);
    g_Xlo[w + 1] = (uint32_t)l2 | ((uint32_t)l3 << 16);
}

// ---------------------------------------------------------------------------
// bf16x3 tensor-core GEMM: g_bufA[128 x 128 per block] = X @ W
// X pre-split in g_Xhi/g_Xlo; W pre-split [n][k] in Whi/Wlo. No conversion here.
#define XPITCH 40

__device__ __forceinline__ void mma_bf16(float* d, const uint32_t* a,
                                         uint32_t b0, uint32_t b1) {
    asm volatile(
        "mma.sync.aligned.m16n8k16.row.col.f32.bf16.bf16.f32 "
        "{%0,%1,%2,%3}, {%4,%5,%6,%7}, {%8,%9}, {%0,%1,%2,%3};"
        : "+f"(d[0]), "+f"(d[1]), "+f"(d[2]), "+f"(d[3])
        : "r"(a[0]), "r"(a[1]), "r"(a[2]), "r"(a[3]), "r"(b0), "r"(b1));
}

__global__ __launch_bounds__(256, 2)
void gemm_mma_kernel(const unsigned short* __restrict__ Whi,
                     const unsigned short* __restrict__ Wlo, int nN) {
    __shared__ __align__(16) unsigned short sXhi[128][XPITCH];
    __shared__ __align__(16) unsigned short sXlo[128][XPITCH];
    __shared__ __align__(16) unsigned short sWhi[128][XPITCH];
    __shared__ __align__(16) unsigned short sWlo[128][XPITCH];

    const int tid  = threadIdx.x;
    const int wid  = tid >> 5;
    const int lane = tid & 31;
    const int g    = lane >> 2;
    const int tig  = lane & 3;
    const int row0 = blockIdx.x * 128;
    const int wm   = wid & 3;
    const int wn   = wid >> 2;
    const uint32_t* Wh32 = (const uint32_t*)Whi;
    const uint32_t* Wl32 = (const uint32_t*)Wlo;

    float acc[2][8][4];
#pragma unroll
    for (int mt = 0; mt < 2; mt++)
#pragma unroll
        for (int nt = 0; nt < 8; nt++)
#pragma unroll
            for (int q = 0; q < 4; q++) acc[mt][nt][q] = 0.f;

    for (int kc = 0; kc < 4; kc++) {
        // stage X chunk: 128 rows x 16 words (hi+lo), 2048 words each
#pragma unroll
        for (int p = 0; p < 8; p++) {
            int idx = p * 256 + tid;        // 0..2047
            int r   = idx >> 4;
            int pp  = idx & 15;
            int grow = row0 + r;
            uint32_t hw = 0, lw = 0;
            if (grow < nN) {
                size_t widx = (size_t)grow * 64 + kc * 16 + pp;
                hw = g_Xhi[widx];
                lw = g_Xlo[widx];
            }
            *(uint32_t*)&sXhi[r][2 * pp] = hw;
            *(uint32_t*)&sXlo[r][2 * pp] = lw;
        }
        // stage W chunk: 128 n x 16 words
#pragma unroll
        for (int p = 0; p < 8; p++) {
            int idx = p * 256 + tid;
            int n   = idx >> 4;
            int pp  = idx & 15;
            int widx = n * 64 + kc * 16 + pp;
            *(uint32_t*)&sWhi[n][2 * pp] = Wh32[widx];
            *(uint32_t*)&sWlo[n][2 * pp] = Wl32[widx];
        }
        __syncthreads();

#pragma unroll
        for (int ks = 0; ks < 2; ks++) {
            int kb = ks * 16;
            uint32_t ah[2][4], al[2][4];
#pragma unroll
            for (int mt = 0; mt < 2; mt++) {
                int r1 = wm * 32 + mt * 16 + g;
                ah[mt][0] = *(const uint32_t*)&sXhi[r1][kb + 2 * tig];
                ah[mt][1] = *(const uint32_t*)&sXhi[r1 + 8][kb + 2 * tig];
                ah[mt][2] = *(const uint32_t*)&sXhi[r1][kb + 8 + 2 * tig];
                ah[mt][3] = *(const uint32_t*)&sXhi[r1 + 8][kb + 8 + 2 * tig];
                al[mt][0] = *(const uint32_t*)&sXlo[r1][kb + 2 * tig];
                al[mt][1] = *(const uint32_t*)&sXlo[r1 + 8][kb + 2 * tig];
                al[mt][2] = *(const uint32_t*)&sXlo[r1][kb + 8 + 2 * tig];
                al[mt][3] = *(const uint32_t*)&sXlo[r1 + 8][kb + 8 + 2 * tig];
            }
#pragma unroll
            for (int nt = 0; nt < 8; nt++) {
                int n = wn * 64 + nt * 8 + g;
                uint32_t bh0 = *(const uint32_t*)&sWhi[n][kb + 2 * tig];
                uint32_t bh1 = *(const uint32_t*)&sWhi[n][kb + 8 + 2 * tig];
                uint32_t bl0 = *(const uint32_t*)&sWlo[n][kb + 2 * tig];
                uint32_t bl1 = *(const uint32_t*)&sWlo[n][kb + 8 + 2 * tig];
#pragma unroll
                for (int mt = 0; mt < 2; mt++) {
                    mma_bf16(acc[mt][nt], ah[mt], bh0, bh1);
                    mma_bf16(acc[mt][nt], ah[mt], bl0, bl1);
                    mma_bf16(acc[mt][nt], al[mt], bh0, bh1);
                }
            }
        }
        __syncthreads();
    }

#pragma unroll
    for (int mt = 0; mt < 2; mt++) {
#pragma unroll
        for (int nt = 0; nt < 8; nt++) {
            int col = wn * 64 + nt * 8 + 2 * tig;
            int r1 = row0 + wm * 32 + mt * 16 + g;
            *(float2*)(g_bufA + (size_t)r1 * F + col) =
                make_float2(acc[mt][nt][0], acc[mt][nt][1]);
            *(float2*)(g_bufA + (size_t)(r1 + 8) * F + col) =
                make_float2(acc[mt][nt][2], acc[mt][nt][3]);
        }
    }
}

// ---------------------------------------------------------------------------
// Gather-1: aggregate + layer-2 transform + bf16 split -> g_Xhi/g_Xlo
__global__ void gather1_kernel(const float* __restrict__ b1, int nN) {
    int node = blockIdx.x * (blockDim.x >> 5) + (threadIdx.x >> 5);
    int lane = threadIdx.x & 31;
    if (node >= nN) return;
    int b = g_off[node];
    int e = b + g_cntIn[node];
    float4 acc = make_float4(0.f, 0.f, 0.f, 0.f);
    int j = b;
    int e4 = b + ((e - b) & ~3);
    for (; j < e4; j += 4) {
        int s0 = g_eidx[j], s1 = g_eidx[j + 1], s2 = g_eidx[j + 2], s3 = g_eidx[j + 3];
        float4 v0 = ((const float4*)(g_bufA + (size_t)s0 * F))[lane];
        float4 v1 = ((const float4*)(g_bufA + (size_t)s1 * F))[lane];
        float4 v2 = ((const float4*)(g_bufA + (size_t)s2 * F))[lane];
        float4 v3 = ((const float4*)(g_bufA + (size_t)s3 * F))[lane];
        acc.x += v0.x + v1.x + v2.x + v3.x;
        acc.y += v0.y + v1.y + v2.y + v3.y;
        acc.z += v0.z + v1.z + v2.z + v3.z;
        acc.w += v0.w + v1.w + v2.w + v3.w;
    }
    for (; j < e; j++) {
        int s = g_eidx[j];
        float4 v = ((const float4*)(g_bufA + (size_t)s * F))[lane];
        acc.x += v.x; acc.y += v.y; acc.z += v.z; acc.w += v.w;
    }
    // transform: relu(acc*dinvIn + b1) * dinvOut, then split
    float db = g_dinvIn[node];
    float da = g_dinvOut[node];
    float4 bb = ((const float4*)b1)[lane];
    float x0 = fmaxf(fmaf(acc.x, db, bb.x), 0.f) * da;
    float x1 = fmaxf(fmaf(acc.y, db, bb.y), 0.f) * da;
    float x2 = fmaxf(fmaf(acc.z, db, bb.z), 0.f) * da;
    float x3 = fmaxf(fmaf(acc.w, db, bb.w), 0.f) * da;
    unsigned short h0, l0, h1, l1, h2, l2, h3, l3;
    split_bf16(x0, h0, l0); split_bf16(x1, h1, l1);
    split_bf16(x2, h2, l2); split_bf16(x3, h3, l3);
    size_t w = (size_t)node * 64 + lane * 2;
    g_Xhi[w]     = (uint32_t)h0 | ((uint32_t)h1 << 16);
    g_Xhi[w + 1] = (uint32_t)h2 | ((uint32_t)h3 << 16);
    g_Xlo[w]     = (uint32_t)l0 | ((uint32_t)l1 << 16);
    g_Xlo[w + 1] = (uint32_t)l2 | ((uint32_t)l3 << 16);
}

// ---------------------------------------------------------------------------
// Gather-2 + fused classifier: out[node][c] = relu(agg*dinvIn+b2) @ Wc + bc
__global__ void gather2_cls_kernel(const float* __restrict__ b2,
                                   const float* __restrict__ Wc,
                                   const float* __restrict__ bc,
                                   float* __restrict__ out, int nN) {
    int node = blockIdx.x * (blockDim.x >> 5) + (threadIdx.x >> 5);
    int lane = threadIdx.x & 31;
    if (node >= nN) return;
    int b = g_off[node];
    int e = b + g_cntIn[node];
    float4 acc = make_float4(0.f, 0.f, 0.f, 0.f);
    int j = b;
    int e4 = b + ((e - b) & ~3);
    for (; j < e4; j += 4) {
        int s0 = g_eidx[j], s1 = g_eidx[j + 1], s2 = g_eidx[j + 2], s3 = g_eidx[j + 3];
        float4 v0 = ((const float4*)(g_bufA + (size_t)s0 * F))[lane];
        float4 v1 = ((const float4*)(g_bufA + (size_t)s1 * F))[lane];
        float4 v2 = ((const float4*)(g_bufA + (size_t)s2 * F))[lane];
        float4 v3 = ((const float4*)(g_bufA + (size_t)s3 * F))[lane];
        acc.x += v0.x + v1.x + v2.x + v3.x;
        acc.y += v0.y + v1.y + v2.y + v3.y;
        acc.z += v0.z + v1.z + v2.z + v3.z;
        acc.w += v0.w + v1.w + v2.w + v3.w;
    }
    for (; j < e; j++) {
        int s = g_eidx[j];
        float4 v = ((const float4*)(g_bufA + (size_t)s * F))[lane];
        acc.x += v.x; acc.y += v.y; acc.z += v.z; acc.w += v.w;
    }
    float db = g_dinvIn[node];
    float4 bb = ((const float4*)b2)[lane];
    float h[4];
    h[0] = fmaxf(fmaf(acc.x, db, bb.x), 0.f);
    h[1] = fmaxf(fmaf(acc.y, db, bb.y), 0.f);
    h[2] = fmaxf(fmaf(acc.z, db, bb.z), 0.f);
    h[3] = fmaxf(fmaf(acc.w, db, bb.w), 0.f);

    float a0 = 0.f, a1 = 0.f, a2 = 0.f, a3 = 0.f;
    const float4* Wc4 = (const float4*)Wc;
#pragma unroll
    for (int q = 0; q < 4; q++) {
        float4 w = Wc4[lane * 4 + q];
        a0 = fmaf(h[q], w.x, a0);
        a1 = fmaf(h[q], w.y, a1);
        a2 = fmaf(h[q], w.z, a2);
        a3 = fmaf(h[q], w.w, a3);
    }
#pragma unroll
    for (int o = 16; o > 0; o >>= 1) {
        a0 += __shfl_xor_sync(0xffffffffu, a0, o);
        a1 += __shfl_xor_sync(0xffffffffu, a1, o);
        a2 += __shfl_xor_sync(0xffffffffu, a2, o);
        a3 += __shfl_xor_sync(0xffffffffu, a3, o);
    }
    if (lane == 0)
        ((float4*)out)[node] = make_float4(a0 + bc[0], a1 + bc[1], a2 + bc[2], a3 + bc[3]);
}

// ---------------------------------------------------------------------------
extern "C" void kernel_launch(void* const* d_in, const int* in_sizes, int n_in,
                              void* d_out, int out_size) {
    const float* features = (const float*)d_in[0];
    const int*   src      = (const int*)d_in[1];
    const int*   dst      = (const int*)d_in[2];
    const float* W1       = (const float*)d_in[3];
    const float* b1       = (const float*)d_in[4];
    const float* W2       = (const float*)d_in[5];
    const float* b2       = (const float*)d_in[6];
    const float* Wc       = (const float*)d_in[7];
    const float* bc       = (const float*)d_in[8];
    float*       out      = (float*)d_out;

    const int nN = in_sizes[0] / F;
    const int nE = in_sizes[1];
    const int nb = (nN + SCAN_B - 1) / SCAN_B;

    unsigned short *w1hi, *w1lo, *w2hi, *w2lo;
    // direct symbol references inside kernels; host just launches

    // degrees + weight prep
    zero_cnt_kernel<<<(nN + 255) / 256, 256>>>(nN);
    hist_kernel<<<(nE + 255) / 256, 256>>>(src, dst, nE);
    dinv_kernel<<<(nN + 255) / 256, 256>>>(nN);
    wsplit_kernel<<<128, 256>>>(W1, W2);
    prep_kernel<<<(nN * 32 + 255) / 256, 256>>>(features, nN);

    // CSR offsets + fill
    scan_block_kernel<<<nb, SCAN_B>>>(nN);
    scan_small_kernel<<<1, 128>>>(nb);
    offsets_kernel<<<(nN + 255) / 256, 256>>>(nN);
    fill_kernel<<<(nE + 255) / 256, 256>>>(src, dst, nE);

    // layer 1: GEMM (pre-split X,W1) -> bufA; gather+transform+split -> Xhi/Xlo
    cudaGetSymbolAddress((void**)&w1hi, g_W1hi);  // harmless host-side lookups
    cudaGetSymbolAddress((void**)&w1lo, g_W1lo);
    cudaGetSymbolAddress((void**)&w2hi, g_W2hi);
    cudaGetSymbolAddress((void**)&w2lo, g_W2lo);
    gemm_mma_kernel<<<(nN + 127) / 128, 256>>>(w1hi, w1lo, nN);
    gather1_kernel<<<(nN + 7) / 8, 256>>>(b1, nN);

    // layer 2: GEMM (Xhi/Xlo, W2) -> bufA; gather + fused classifier -> out
    gemm_mma_kernel<<<(nN + 127) / 128, 256>>>(w2hi, w2lo, nN);
    gather2_cls_kernel<<<(nN + 7) / 8, 256>>>(b2, Wc, bc, out, nN);
}

// round 8
// speedup vs baseline: 1.2502x; 1.0033x over previous
#include <cuda_runtime.h>
#include <cuda_bf16.h>
#include <cstdint>

#define F 128
#define MAXN 100000
#define MAXNP 100096   // padded to multiple of 128 (GEMM tile)
#define MAXE 1600000
#define SCAN_B 1024
#define MAXBLK ((MAXN + SCAN_B - 1) / SCAN_B)   // 98

// Scratch (allocation-free: __device__ globals)
__device__ __align__(16) float    g_bufA[(size_t)MAXNP * F];       // 51.2 MB
__device__ __align__(16) uint32_t g_Xhi[(size_t)MAXNP * (F / 2)];  // 25.6 MB (bf16 pairs)
__device__ __align__(16) uint32_t g_Xlo[(size_t)MAXNP * (F / 2)];  // 25.6 MB
__device__ __align__(4) unsigned short g_W1hi[F * F];  // [n][k] transposed
__device__ __align__(4) unsigned short g_W1lo[F * F];
__device__ __align__(4) unsigned short g_W2hi[F * F];
__device__ __align__(4) unsigned short g_W2lo[F * F];
__device__ int   g_cntIn[MAXN];
__device__ int   g_cntOut[MAXN];
__device__ int   g_excl[MAXN];
__device__ int   g_bsum[MAXBLK];
__device__ int   g_off[MAXN];
__device__ int   g_cursor[MAXN];
__device__ int   g_eidx[MAXE];
__device__ float g_dinvOut[MAXN];
__device__ float g_dinvIn[MAXN];

__device__ __forceinline__ void split_bf16(float v, unsigned short& h, unsigned short& l) {
    __nv_bfloat16 hb = __float2bfloat16(v);
    __nv_bfloat16 lb = __float2bfloat16(v - __bfloat162float(hb));
    h = __bfloat16_as_ushort(hb);
    l = __bfloat16_as_ushort(lb);
}

// ---------------------------------------------------------------------------
__global__ void zero_cnt_kernel(int n) {
    int i = blockIdx.x * blockDim.x + threadIdx.x;
    if (i < n) { g_cntIn[i] = 0; g_cntOut[i] = 0; }
}

// 2 edges per thread via int2
__global__ void hist_kernel(const int2* __restrict__ src2,
                            const int2* __restrict__ dst2, int nE2, int odd,
                            const int* __restrict__ src,
                            const int* __restrict__ dst) {
    int i = blockIdx.x * blockDim.x + threadIdx.x;
    if (i < nE2) {
        int2 s = src2[i];
        int2 d = dst2[i];
        atomicAdd(&g_cntOut[s.x], 1);
        atomicAdd(&g_cntOut[s.y], 1);
        atomicAdd(&g_cntIn[d.x], 1);
        atomicAdd(&g_cntIn[d.y], 1);
    } else if (i == nE2 && odd) {
        atomicAdd(&g_cntOut[src[2 * nE2]], 1);
        atomicAdd(&g_cntIn[dst[2 * nE2]], 1);
    }
}

__global__ void dinv_kernel(int n) {
    int i = blockIdx.x * blockDim.x + threadIdx.x;
    if (i < n) {
        g_dinvIn[i]  = rsqrtf(fmaxf((float)g_cntIn[i],  1.f));
        g_dinvOut[i] = rsqrtf(fmaxf((float)g_cntOut[i], 1.f));
    }
}

__global__ void scan_block_kernel(int n) {
    __shared__ int s[SCAN_B];
    int tid = threadIdx.x;
    int i = blockIdx.x * SCAN_B + tid;
    int v = (i < n) ? g_cntIn[i] : 0;
    s[tid] = v;
    __syncthreads();
#pragma unroll
    for (int o = 1; o < SCAN_B; o <<= 1) {
        int t = (tid >= o) ? s[tid - o] : 0;
        __syncthreads();
        s[tid] += t;
        __syncthreads();
    }
    if (i < n) g_excl[i] = s[tid] - v;
    if (tid == SCAN_B - 1) g_bsum[blockIdx.x] = s[tid];
}

__global__ void scan_small_kernel(int nb) {
    __shared__ int s[128];
    int tid = threadIdx.x;
    int v = (tid < nb) ? g_bsum[tid] : 0;
    s[tid] = v;
    __syncthreads();
#pragma unroll
    for (int o = 1; o < 128; o <<= 1) {
        int t = (tid >= o) ? s[tid - o] : 0;
        __syncthreads();
        s[tid] += t;
        __syncthreads();
    }
    if (tid < nb) g_bsum[tid] = s[tid] - v;
}

__global__ void offsets_kernel(int n) {
    int i = blockIdx.x * blockDim.x + threadIdx.x;
    if (i < n) {
        int o = g_excl[i] + g_bsum[i / SCAN_B];
        g_off[i] = o;
        g_cursor[i] = o;
    }
}

__global__ void fill_kernel(const int2* __restrict__ src2,
                            const int2* __restrict__ dst2, int nE2, int odd,
                            const int* __restrict__ src,
                            const int* __restrict__ dst) {
    int i = blockIdx.x * blockDim.x + threadIdx.x;
    if (i < nE2) {
        int2 s = src2[i];
        int2 d = dst2[i];
        int p0 = atomicAdd(&g_cursor[d.x], 1);
        g_eidx[p0] = s.x;
        int p1 = atomicAdd(&g_cursor[d.y], 1);
        g_eidx[p1] = s.y;
    } else if (i == nE2 && odd) {
        int p = atomicAdd(&g_cursor[dst[2 * nE2]], 1);
        g_eidx[p] = src[2 * nE2];
    }
}

// ---------------------------------------------------------------------------
// Pre-split both weight matrices, transposed to [n][k]
__global__ void wsplit_kernel(const float* __restrict__ W1,
                              const float* __restrict__ W2) {
    int t = blockIdx.x * blockDim.x + threadIdx.x;   // 0..32767
    int which = t >> 14;
    int i = t & 16383;
    int k = i >> 7, n = i & 127;
    unsigned short h, l;
    if (which == 0) {
        split_bf16(W1[i], h, l);
        g_W1hi[n * F + k] = h; g_W1lo[n * F + k] = l;
    } else {
        split_bf16(W2[i], h, l);
        g_W2hi[n * F + k] = h; g_W2lo[n * F + k] = l;
    }
}

// features * dinvOut -> split bf16 hi/lo (layer-1 GEMM input)
__global__ void prep_kernel(const float* __restrict__ feat, int nN) {
    int i = blockIdx.x * blockDim.x + threadIdx.x;   // one float4 each
    if (i >= nN * 32) return;
    int row = i >> 5, c4 = i & 31;
    float4 v = ((const float4*)feat)[i];
    float da = g_dinvOut[row];
    v.x *= da; v.y *= da; v.z *= da; v.w *= da;
    unsigned short h0, l0, h1, l1, h2, l2, h3, l3;
    split_bf16(v.x, h0, l0); split_bf16(v.y, h1, l1);
    split_bf16(v.z, h2, l2); split_bf16(v.w, h3, l3);
    size_t w = (size_t)row * 64 + c4 * 2;
    g_Xhi[w]     = (uint32_t)h0 | ((uint32_t)h1 << 16);
    g_Xhi[w + 1] = (uint32_t)h2 | ((uint32_t)h3 << 16);
    g_Xlo[w]     = (uint32_t)l0 | ((uint32_t)l1 << 16);
    g_Xlo[w + 1] = (uint32_t)l2 | ((uint32_t)l3 << 16);
}

// ---------------------------------------------------------------------------
// bf16x3 tensor-core GEMM with ldmatrix fragment loads.
#define XPITCH 40   // shorts per row: 80B = 5x16B -> LDSM rows conflict-free

__device__ __forceinline__ void mma_bf16(float* d, const uint32_t* a,
                                         uint32_t b0, uint32_t b1) {
    asm volatile(
        "mma.sync.aligned.m16n8k16.row.col.f32.bf16.bf16.f32 "
        "{%0,%1,%2,%3}, {%4,%5,%6,%7}, {%8,%9}, {%0,%1,%2,%3};"
        : "+f"(d[0]), "+f"(d[1]), "+f"(d[2]), "+f"(d[3])
        : "r"(a[0]), "r"(a[1]), "r"(a[2]), "r"(a[3]), "r"(b0), "r"(b1));
}

__device__ __forceinline__ void ldsm_x4(uint32_t& r0, uint32_t& r1,
                                        uint32_t& r2, uint32_t& r3,
                                        const void* p) {
    uint32_t a = (uint32_t)__cvta_generic_to_shared(p);
    asm volatile("ldmatrix.sync.aligned.m8n8.x4.shared.b16 {%0,%1,%2,%3}, [%4];"
                 : "=r"(r0), "=r"(r1), "=r"(r2), "=r"(r3) : "r"(a));
}

__global__ __launch_bounds__(256, 2)
void gemm_mma_kernel(const unsigned short* __restrict__ Whi,
                     const unsigned short* __restrict__ Wlo, int nN) {
    __shared__ __align__(16) unsigned short sXhi[128][XPITCH];
    __shared__ __align__(16) unsigned short sXlo[128][XPITCH];
    __shared__ __align__(16) unsigned short sWhi[128][XPITCH];
    __shared__ __align__(16) unsigned short sWlo[128][XPITCH];

    const int tid  = threadIdx.x;
    const int wid  = tid >> 5;
    const int lane = tid & 31;
    const int g    = lane >> 2;
    const int tig  = lane & 3;
    const int row0 = blockIdx.x * 128;
    const int wm   = wid & 3;
    const int wn   = wid >> 2;
    const uint32_t* Wh32 = (const uint32_t*)Whi;
    const uint32_t* Wl32 = (const uint32_t*)Wlo;

    // ldmatrix lane -> (row offset, k offset) within a 16x16 fragment group
    const int lrow = (lane & 7) + ((lane >> 3) & 1) * 8;
    const int lcol = (lane >> 4) * 8;

    float acc[2][8][4];
#pragma unroll
    for (int mt = 0; mt < 2; mt++)
#pragma unroll
        for (int nt = 0; nt < 8; nt++)
#pragma unroll
            for (int q = 0; q < 4; q++) acc[mt][nt][q] = 0.f;

    for (int kc = 0; kc < 4; kc++) {
        // stage X chunk: 128 rows x 16 words (hi+lo)
#pragma unroll
        for (int p = 0; p < 8; p++) {
            int idx = p * 256 + tid;        // 0..2047
            int r   = idx >> 4;
            int pp  = idx & 15;
            int grow = row0 + r;
            uint32_t hw = 0, lw = 0;
            if (grow < nN) {
                size_t widx = (size_t)grow * 64 + kc * 16 + pp;
                hw = g_Xhi[widx];
                lw = g_Xlo[widx];
            }
            *(uint32_t*)&sXhi[r][2 * pp] = hw;
            *(uint32_t*)&sXlo[r][2 * pp] = lw;
        }
        // stage W chunk: 128 n x 16 words
#pragma unroll
        for (int p = 0; p < 8; p++) {
            int idx = p * 256 + tid;
            int n   = idx >> 4;
            int pp  = idx & 15;
            int widx = n * 64 + kc * 16 + pp;
            *(uint32_t*)&sWhi[n][2 * pp] = Wh32[widx];
            *(uint32_t*)&sWlo[n][2 * pp] = Wl32[widx];
        }
        __syncthreads();

#pragma unroll
        for (int ks = 0; ks < 2; ks++) {
            int kb = ks * 16;
            uint32_t ah[2][4], al[2][4];
#pragma unroll
            for (int mt = 0; mt < 2; mt++) {
                int rb = wm * 32 + mt * 16;
                ldsm_x4(ah[mt][0], ah[mt][1], ah[mt][2], ah[mt][3],
                        &sXhi[rb + lrow][kb + lcol]);
                ldsm_x4(al[mt][0], al[mt][1], al[mt][2], al[mt][3],
                        &sXlo[rb + lrow][kb + lcol]);
            }
#pragma unroll
            for (int ntp = 0; ntp < 4; ntp++) {
                int n0 = wn * 64 + ntp * 16;
                uint32_t bh[4], bl[4];
                // bh[0]=b0(nt=2ntp), bh[1]=b0(nt=2ntp+1), bh[2]=b1(nt), bh[3]=b1(nt+1)
                ldsm_x4(bh[0], bh[1], bh[2], bh[3], &sWhi[n0 + lrow][kb + lcol]);
                ldsm_x4(bl[0], bl[1], bl[2], bl[3], &sWlo[n0 + lrow][kb + lcol]);
#pragma unroll
                for (int sub = 0; sub < 2; sub++) {
                    int nt = 2 * ntp + sub;
#pragma unroll
                    for (int mt = 0; mt < 2; mt++) {
                        mma_bf16(acc[mt][nt], ah[mt], bh[sub], bh[2 + sub]);
                        mma_bf16(acc[mt][nt], ah[mt], bl[sub], bl[2 + sub]);
                        mma_bf16(acc[mt][nt], al[mt], bh[sub], bh[2 + sub]);
                    }
                }
            }
        }
        __syncthreads();
    }

#pragma unroll
    for (int mt = 0; mt < 2; mt++) {
#pragma unroll
        for (int nt = 0; nt < 8; nt++) {
            int col = wn * 64 + nt * 8 + 2 * tig;
            int r1 = row0 + wm * 32 + mt * 16 + g;
            *(float2*)(g_bufA + (size_t)r1 * F + col) =
                make_float2(acc[mt][nt][0], acc[mt][nt][1]);
            *(float2*)(g_bufA + (size_t)(r1 + 8) * F + col) =
                make_float2(acc[mt][nt][2], acc[mt][nt][3]);
        }
    }
}

// ---------------------------------------------------------------------------
// Gather-1: aggregate + layer-2 transform + bf16 split -> g_Xhi/g_Xlo
__global__ void gather1_kernel(const float* __restrict__ b1, int nN) {
    int node = blockIdx.x * (blockDim.x >> 5) + (threadIdx.x >> 5);
    int lane = threadIdx.x & 31;
    if (node >= nN) return;
    int b = g_off[node];
    int e = b + g_cntIn[node];
    float4 acc = make_float4(0.f, 0.f, 0.f, 0.f);
    int j = b;
    int e4 = b + ((e - b) & ~3);
    for (; j < e4; j += 4) {
        int s0 = g_eidx[j], s1 = g_eidx[j + 1], s2 = g_eidx[j + 2], s3 = g_eidx[j + 3];
        float4 v0 = ((const float4*)(g_bufA + (size_t)s0 * F))[lane];
        float4 v1 = ((const float4*)(g_bufA + (size_t)s1 * F))[lane];
        float4 v2 = ((const float4*)(g_bufA + (size_t)s2 * F))[lane];
        float4 v3 = ((const float4*)(g_bufA + (size_t)s3 * F))[lane];
        acc.x += v0.x + v1.x + v2.x + v3.x;
        acc.y += v0.y + v1.y + v2.y + v3.y;
        acc.z += v0.z + v1.z + v2.z + v3.z;
        acc.w += v0.w + v1.w + v2.w + v3.w;
    }
    for (; j < e; j++) {
        int s = g_eidx[j];
        float4 v = ((const float4*)(g_bufA + (size_t)s * F))[lane];
        acc.x += v.x; acc.y += v.y; acc.z += v.z; acc.w += v.w;
    }
    float db = g_dinvIn[node];
    float da = g_dinvOut[node];
    float4 bb = ((const float4*)b1)[lane];
    float x0 = fmaxf(fmaf(acc.x, db, bb.x), 0.f) * da;
    float x1 = fmaxf(fmaf(acc.y, db, bb.y), 0.f) * da;
    float x2 = fmaxf(fmaf(acc.z, db, bb.z), 0.f) * da;
    float x3 = fmaxf(fmaf(acc.w, db, bb.w), 0.f) * da;
    unsigned short h0, l0, h1, l1, h2, l2, h3, l3;
    split_bf16(x0, h0, l0); split_bf16(x1, h1, l1);
    split_bf16(x2, h2, l2); split_bf16(x3, h3, l3);
    size_t w = (size_t)node * 64 + lane * 2;
    g_Xhi[w]     = (uint32_t)h0 | ((uint32_t)h1 << 16);
    g_Xhi[w + 1] = (uint32_t)h2 | ((uint32_t)h3 << 16);
    g_Xlo[w]     = (uint32_t)l0 | ((uint32_t)l1 << 16);
    g_Xlo[w + 1] = (uint32_t)l2 | ((uint32_t)l3 << 16);
}

// ---------------------------------------------------------------------------
// Gather-2 + fused classifier
__global__ void gather2_cls_kernel(const float* __restrict__ b2,
                                   const float* __restrict__ Wc,
                                   const float* __restrict__ bc,
                                   float* __restrict__ out, int nN) {
    int node = blockIdx.x * (blockDim.x >> 5) + (threadIdx.x >> 5);
    int lane = threadIdx.x & 31;
    if (node >= nN) return;
    int b = g_off[node];
    int e = b + g_cntIn[node];
    float4 acc = make_float4(0.f, 0.f, 0.f, 0.f);
    int j = b;
    int e4 = b + ((e - b) & ~3);
    for (; j < e4; j += 4) {
        int s0 = g_eidx[j], s1 = g_eidx[j + 1], s2 = g_eidx[j + 2], s3 = g_eidx[j + 3];
        float4 v0 = ((const float4*)(g_bufA + (size_t)s0 * F))[lane];
        float4 v1 = ((const float4*)(g_bufA + (size_t)s1 * F))[lane];
        float4 v2 = ((const float4*)(g_bufA + (size_t)s2 * F))[lane];
        float4 v3 = ((const float4*)(g_bufA + (size_t)s3 * F))[lane];
        acc.x += v0.x + v1.x + v2.x + v3.x;
        acc.y += v0.y + v1.y + v2.y + v3.y;
        acc.z += v0.z + v1.z + v2.z + v3.z;
        acc.w += v0.w + v1.w + v2.w + v3.w;
    }
    for (; j < e; j++) {
        int s = g_eidx[j];
        float4 v = ((const float4*)(g_bufA + (size_t)s * F))[lane];
        acc.x += v.x; acc.y += v.y; acc.z += v.z; acc.w += v.w;
    }
    float db = g_dinvIn[node];
    float4 bb = ((const float4*)b2)[lane];
    float h[4];
    h[0] = fmaxf(fmaf(acc.x, db, bb.x), 0.f);
    h[1] = fmaxf(fmaf(acc.y, db, bb.y), 0.f);
    h[2] = fmaxf(fmaf(acc.z, db, bb.z), 0.f);
    h[3] = fmaxf(fmaf(acc.w, db, bb.w), 0.f);

    float a0 = 0.f, a1 = 0.f, a2 = 0.f, a3 = 0.f;
    const float4* Wc4 = (const float4*)Wc;
#pragma unroll
    for (int q = 0; q < 4; q++) {
        float4 w = Wc4[lane * 4 + q];
        a0 = fmaf(h[q], w.x, a0);
        a1 = fmaf(h[q], w.y, a1);
        a2 = fmaf(h[q], w.z, a2);
        a3 = fmaf(h[q], w.w, a3);
    }
#pragma unroll
    for (int o = 16; o > 0; o >>= 1) {
        a0 += __shfl_xor_sync(0xffffffffu, a0, o);
        a1 += __shfl_xor_sync(0xffffffffu, a1, o);
        a2 += __shfl_xor_sync(0xffffffffu, a2, o);
        a3 += __shfl_xor_sync(0xffffffffu, a3, o);
    }
    if (lane == 0)
        ((float4*)out)[node] = make_float4(a0 + bc[0], a1 + bc[1], a2 + bc[2], a3 + bc[3]);
}

// ---------------------------------------------------------------------------
extern "C" void kernel_launch(void* const* d_in, const int* in_sizes, int n_in,
                              void* d_out, int out_size) {
    const float* features = (const float*)d_in[0];
    const int*   src      = (const int*)d_in[1];
    const int*   dst      = (const int*)d_in[2];
    const float* W1       = (const float*)d_in[3];
    const float* b1       = (const float*)d_in[4];
    const float* W2       = (const float*)d_in[5];
    const float* b2       = (const float*)d_in[6];
    const float* Wc       = (const float*)d_in[7];
    const float* bc       = (const float*)d_in[8];
    float*       out      = (float*)d_out;

    const int nN  = in_sizes[0] / F;
    const int nE  = in_sizes[1];
    const int nb  = (nN + SCAN_B - 1) / SCAN_B;
    const int nE2 = nE >> 1;
    const int odd = nE & 1;

    unsigned short *w1hi, *w1lo, *w2hi, *w2lo;
    cudaGetSymbolAddress((void**)&w1hi, g_W1hi);
    cudaGetSymbolAddress((void**)&w1lo, g_W1lo);
    cudaGetSymbolAddress((void**)&w2hi, g_W2hi);
    cudaGetSymbolAddress((void**)&w2lo, g_W2lo);

    // degrees + weight/feature prep
    zero_cnt_kernel<<<(nN + 255) / 256, 256>>>(nN);
    hist_kernel<<<(nE2 + 256) / 256, 256>>>((const int2*)src, (const int2*)dst,
                                            nE2, odd, src, dst);
    dinv_kernel<<<(nN + 255) / 256, 256>>>(nN);
    wsplit_kernel<<<128, 256>>>(W1, W2);
    prep_kernel<<<(nN * 32 + 255) / 256, 256>>>(features, nN);

    // CSR offsets + fill
    scan_block_kernel<<<nb, SCAN_B>>>(nN);
    scan_small_kernel<<<1, 128>>>(nb);
    offsets_kernel<<<(nN + 255) / 256, 256>>>(nN);
    fill_kernel<<<(nE2 + 256) / 256, 256>>>((const int2*)src, (const int2*)dst,
                                            nE2, odd, src, dst);

    // layer 1
    gemm_mma_kernel<<<(nN + 127) / 128, 256>>>(w1hi, w1lo, nN);
    gather1_kernel<<<(nN + 7) / 8, 256>>>(b1, nN);

    // layer 2 + fused classifier
    gemm_mma_kernel<<<(nN + 127) / 128, 256>>>(w2hi, w2lo, nN);
    gather2_cls_kernel<<<(nN + 7) / 8, 256>>>(b2, Wc, bc, out, nN);
}

// round 9
// speedup vs baseline: 1.3084x; 1.0466x over previous
#include <cuda_runtime.h>
#include <cuda_bf16.h>
#include <cstdint>

#define F 128
#define MAXN 100000
#define MAXNP 100096   // padded to multiple of 128 (GEMM tile)
#define MAXE 1600000
#define SCAN_B 1024
#define MAXBLK ((MAXN + SCAN_B - 1) / SCAN_B)   // 98

// Scratch (allocation-free: __device__ globals)
__device__ __align__(16) float    g_bufA[(size_t)MAXNP * F];       // 51.2 MB
__device__ __align__(16) uint32_t g_Xhi[(size_t)MAXNP * (F / 2)];  // 25.6 MB (bf16 pairs)
__device__ __align__(16) uint32_t g_Xlo[(size_t)MAXNP * (F / 2)];  // 25.6 MB
__device__ __align__(4) unsigned short g_W1hi[F * F];  // [n][k] transposed
__device__ __align__(4) unsigned short g_W1lo[F * F];
__device__ __align__(4) unsigned short g_W2hi[F * F];
__device__ __align__(4) unsigned short g_W2lo[F * F];
__device__ int   g_cntIn[MAXN];
__device__ int   g_cntOut[MAXN];
__device__ int   g_excl[MAXN];
__device__ int   g_bsum[MAXBLK];
__device__ int   g_off[MAXN];
__device__ int   g_cursor[MAXN];
__device__ int   g_eidx[MAXE];
__device__ float g_dinvOut[MAXN];
__device__ float g_dinvIn[MAXN];

__device__ __forceinline__ void split_bf16(float v, unsigned short& h, unsigned short& l) {
    __nv_bfloat16 hb = __float2bfloat16(v);
    __nv_bfloat16 lb = __float2bfloat16(v - __bfloat162float(hb));
    h = __bfloat16_as_ushort(hb);
    l = __bfloat16_as_ushort(lb);
}

// ---------------------------------------------------------------------------
__global__ void zero_cnt_kernel(int n) {
    int i = blockIdx.x * blockDim.x + threadIdx.x;
    if (i < n) { g_cntIn[i] = 0; g_cntOut[i] = 0; }
}

// 2 edges per thread via int2
__global__ void hist_kernel(const int2* __restrict__ src2,
                            const int2* __restrict__ dst2, int nE2, int odd,
                            const int* __restrict__ src,
                            const int* __restrict__ dst) {
    int i = blockIdx.x * blockDim.x + threadIdx.x;
    if (i < nE2) {
        int2 s = src2[i];
        int2 d = dst2[i];
        atomicAdd(&g_cntOut[s.x], 1);
        atomicAdd(&g_cntOut[s.y], 1);
        atomicAdd(&g_cntIn[d.x], 1);
        atomicAdd(&g_cntIn[d.y], 1);
    } else if (i == nE2 && odd) {
        atomicAdd(&g_cntOut[src[2 * nE2]], 1);
        atomicAdd(&g_cntIn[dst[2 * nE2]], 1);
    }
}

__global__ void dinv_kernel(int n) {
    int i = blockIdx.x * blockDim.x + threadIdx.x;
    if (i < n) {
        g_dinvIn[i]  = rsqrtf(fmaxf((float)g_cntIn[i],  1.f));
        g_dinvOut[i] = rsqrtf(fmaxf((float)g_cntOut[i], 1.f));
    }
}

// Shuffle-based block scan (2 barriers)
__global__ void scan_block_kernel(int n) {
    __shared__ int wsum[32];
    int tid = threadIdx.x, lane = tid & 31, w = tid >> 5;
    int i = blockIdx.x * SCAN_B + tid;
    int v = (i < n) ? g_cntIn[i] : 0;
    int x = v;
#pragma unroll
    for (int o = 1; o < 32; o <<= 1) {
        int t = __shfl_up_sync(0xffffffffu, x, o);
        if (lane >= o) x += t;
    }
    if (lane == 31) wsum[w] = x;
    __syncthreads();
    if (w == 0) {
        int s = wsum[lane];
#pragma unroll
        for (int o = 1; o < 32; o <<= 1) {
            int t = __shfl_up_sync(0xffffffffu, s, o);
            if (lane >= o) s += t;
        }
        wsum[lane] = s;
    }
    __syncthreads();
    int incl = x + ((w > 0) ? wsum[w - 1] : 0);
    if (i < n) g_excl[i] = incl - v;
    if (tid == SCAN_B - 1) g_bsum[blockIdx.x] = incl;
}

// Exclusive scan of block sums (nb <= 128): 4 warps, shuffle-based
__global__ void scan_small_kernel(int nb) {
    __shared__ int wsum[4];
    int tid = threadIdx.x, lane = tid & 31, w = tid >> 5;
    int v = (tid < nb) ? g_bsum[tid] : 0;
    int x = v;
#pragma unroll
    for (int o = 1; o < 32; o <<= 1) {
        int t = __shfl_up_sync(0xffffffffu, x, o);
        if (lane >= o) x += t;
    }
    if (lane == 31) wsum[w] = x;
    __syncthreads();
    int base = 0;
#pragma unroll
    for (int q = 0; q < 4; q++) base += (q < w) ? wsum[q] : 0;
    if (tid < nb) g_bsum[tid] = base + x - v;
}

__global__ void offsets_kernel(int n) {
    int i = blockIdx.x * blockDim.x + threadIdx.x;
    if (i < n) {
        int o = g_excl[i] + g_bsum[i / SCAN_B];
        g_off[i] = o;
        g_cursor[i] = o;
    }
}

__global__ void fill_kernel(const int2* __restrict__ src2,
                            const int2* __restrict__ dst2, int nE2, int odd,
                            const int* __restrict__ src,
                            const int* __restrict__ dst) {
    int i = blockIdx.x * blockDim.x + threadIdx.x;
    if (i < nE2) {
        int2 s = src2[i];
        int2 d = dst2[i];
        int p0 = atomicAdd(&g_cursor[d.x], 1);
        g_eidx[p0] = s.x;
        int p1 = atomicAdd(&g_cursor[d.y], 1);
        g_eidx[p1] = s.y;
    } else if (i == nE2 && odd) {
        int p = atomicAdd(&g_cursor[dst[2 * nE2]], 1);
        g_eidx[p] = src[2 * nE2];
    }
}

// ---------------------------------------------------------------------------
__global__ void wsplit_kernel(const float* __restrict__ W1,
                              const float* __restrict__ W2) {
    int t = blockIdx.x * blockDim.x + threadIdx.x;   // 0..32767
    int which = t >> 14;
    int i = t & 16383;
    int k = i >> 7, n = i & 127;
    unsigned short h, l;
    if (which == 0) {
        split_bf16(W1[i], h, l);
        g_W1hi[n * F + k] = h; g_W1lo[n * F + k] = l;
    } else {
        split_bf16(W2[i], h, l);
        g_W2hi[n * F + k] = h; g_W2lo[n * F + k] = l;
    }
}

// features * dinvOut -> split bf16 hi/lo (layer-1 GEMM input)
__global__ void prep_kernel(const float* __restrict__ feat, int nN) {
    int i = blockIdx.x * blockDim.x + threadIdx.x;   // one float4 each
    if (i >= nN * 32) return;
    int row = i >> 5, c4 = i & 31;
    float4 v = ((const float4*)feat)[i];
    float da = g_dinvOut[row];
    v.x *= da; v.y *= da; v.z *= da; v.w *= da;
    unsigned short h0, l0, h1, l1, h2, l2, h3, l3;
    split_bf16(v.x, h0, l0); split_bf16(v.y, h1, l1);
    split_bf16(v.z, h2, l2); split_bf16(v.w, h3, l3);
    size_t w = (size_t)row * 64 + c4 * 2;
    g_Xhi[w]     = (uint32_t)h0 | ((uint32_t)h1 << 16);
    g_Xhi[w + 1] = (uint32_t)h2 | ((uint32_t)h3 << 16);
    g_Xlo[w]     = (uint32_t)l0 | ((uint32_t)l1 << 16);
    g_Xlo[w + 1] = (uint32_t)l2 | ((uint32_t)l3 << 16);
}

// ---------------------------------------------------------------------------
// bf16x3 tensor-core GEMM with ldmatrix fragment loads.
#define XPITCH 40

__device__ __forceinline__ void mma_bf16(float* d, const uint32_t* a,
                                         uint32_t b0, uint32_t b1) {
    asm volatile(
        "mma.sync.aligned.m16n8k16.row.col.f32.bf16.bf16.f32 "
        "{%0,%1,%2,%3}, {%4,%5,%6,%7}, {%8,%9}, {%0,%1,%2,%3};"
        : "+f"(d[0]), "+f"(d[1]), "+f"(d[2]), "+f"(d[3])
        : "r"(a[0]), "r"(a[1]), "r"(a[2]), "r"(a[3]), "r"(b0), "r"(b1));
}

__device__ __forceinline__ void ldsm_x4(uint32_t& r0, uint32_t& r1,
                                        uint32_t& r2, uint32_t& r3,
                                        const void* p) {
    uint32_t a = (uint32_t)__cvta_generic_to_shared(p);
    asm volatile("ldmatrix.sync.aligned.m8n8.x4.shared.b16 {%0,%1,%2,%3}, [%4];"
                 : "=r"(r0), "=r"(r1), "=r"(r2), "=r"(r3) : "r"(a));
}

__global__ __launch_bounds__(256, 2)
void gemm_mma_kernel(const unsigned short* __restrict__ Whi,
                     const unsigned short* __restrict__ Wlo, int nN) {
    __shared__ __align__(16) unsigned short sXhi[128][XPITCH];
    __shared__ __align__(16) unsigned short sXlo[128][XPITCH];
    __shared__ __align__(16) unsigned short sWhi[128][XPITCH];
    __shared__ __align__(16) unsigned short sWlo[128][XPITCH];

    const int tid  = threadIdx.x;
    const int wid  = tid >> 5;
    const int lane = tid & 31;
    const int g    = lane >> 2;
    const int tig  = lane & 3;
    const int row0 = blockIdx.x * 128;
    const int wm   = wid & 3;
    const int wn   = wid >> 2;
    const uint32_t* Wh32 = (const uint32_t*)Whi;
    const uint32_t* Wl32 = (const uint32_t*)Wlo;

    const int lrow = (lane & 7) + ((lane >> 3) & 1) * 8;
    const int lcol = (lane >> 4) * 8;

    float acc[2][8][4];
#pragma unroll
    for (int mt = 0; mt < 2; mt++)
#pragma unroll
        for (int nt = 0; nt < 8; nt++)
#pragma unroll
            for (int q = 0; q < 4; q++) acc[mt][nt][q] = 0.f;

    for (int kc = 0; kc < 4; kc++) {
#pragma unroll
        for (int p = 0; p < 8; p++) {
            int idx = p * 256 + tid;
            int r   = idx >> 4;
            int pp  = idx & 15;
            int grow = row0 + r;
            uint32_t hw = 0, lw = 0;
            if (grow < nN) {
                size_t widx = (size_t)grow * 64 + kc * 16 + pp;
                hw = g_Xhi[widx];
                lw = g_Xlo[widx];
            }
            *(uint32_t*)&sXhi[r][2 * pp] = hw;
            *(uint32_t*)&sXlo[r][2 * pp] = lw;
        }
#pragma unroll
        for (int p = 0; p < 8; p++) {
            int idx = p * 256 + tid;
            int n   = idx >> 4;
            int pp  = idx & 15;
            int widx = n * 64 + kc * 16 + pp;
            *(uint32_t*)&sWhi[n][2 * pp] = Wh32[widx];
            *(uint32_t*)&sWlo[n][2 * pp] = Wl32[widx];
        }
        __syncthreads();

#pragma unroll
        for (int ks = 0; ks < 2; ks++) {
            int kb = ks * 16;
            uint32_t ah[2][4], al[2][4];
#pragma unroll
            for (int mt = 0; mt < 2; mt++) {
                int rb = wm * 32 + mt * 16;
                ldsm_x4(ah[mt][0], ah[mt][1], ah[mt][2], ah[mt][3],
                        &sXhi[rb + lrow][kb + lcol]);
                ldsm_x4(al[mt][0], al[mt][1], al[mt][2], al[mt][3],
                        &sXlo[rb + lrow][kb + lcol]);
            }
#pragma unroll
            for (int ntp = 0; ntp < 4; ntp++) {
                int n0 = wn * 64 + ntp * 16;
                uint32_t bh[4], bl[4];
                ldsm_x4(bh[0], bh[1], bh[2], bh[3], &sWhi[n0 + lrow][kb + lcol]);
                ldsm_x4(bl[0], bl[1], bl[2], bl[3], &sWlo[n0 + lrow][kb + lcol]);
#pragma unroll
                for (int sub = 0; sub < 2; sub++) {
                    int nt = 2 * ntp + sub;
#pragma unroll
                    for (int mt = 0; mt < 2; mt++) {
                        mma_bf16(acc[mt][nt], ah[mt], bh[sub], bh[2 + sub]);
                        mma_bf16(acc[mt][nt], ah[mt], bl[sub], bl[2 + sub]);
                        mma_bf16(acc[mt][nt], al[mt], bh[sub], bh[2 + sub]);
                    }
                }
            }
        }
        __syncthreads();
    }

#pragma unroll
    for (int mt = 0; mt < 2; mt++) {
#pragma unroll
        for (int nt = 0; nt < 8; nt++) {
            int col = wn * 64 + nt * 8 + 2 * tig;
            int r1 = row0 + wm * 32 + mt * 16 + g;
            *(float2*)(g_bufA + (size_t)r1 * F + col) =
                make_float2(acc[mt][nt][0], acc[mt][nt][1]);
            *(float2*)(g_bufA + (size_t)(r1 + 8) * F + col) =
                make_float2(acc[mt][nt][2], acc[mt][nt][3]);
        }
    }
}

// ---------------------------------------------------------------------------
// Gather-1: aggregate (unroll 8) + layer-2 transform + bf16 split -> g_Xhi/g_Xlo
__global__ void gather1_kernel(const float* __restrict__ b1, int nN) {
    int node = blockIdx.x * (blockDim.x >> 5) + (threadIdx.x >> 5);
    int lane = threadIdx.x & 31;
    if (node >= nN) return;
    int b = g_off[node];
    int e = b + g_cntIn[node];
    float4 acc = make_float4(0.f, 0.f, 0.f, 0.f);
    int j = b;
    int e8 = b + ((e - b) & ~7);
    for (; j < e8; j += 8) {
        float4 v[8];
#pragma unroll
        for (int q = 0; q < 8; q++) {
            int s = g_eidx[j + q];
            v[q] = ((const float4*)(g_bufA + (size_t)s * F))[lane];
        }
#pragma unroll
        for (int q = 0; q < 8; q++) {
            acc.x += v[q].x; acc.y += v[q].y; acc.z += v[q].z; acc.w += v[q].w;
        }
    }
    for (; j < e; j++) {
        int s = g_eidx[j];
        float4 v = ((const float4*)(g_bufA + (size_t)s * F))[lane];
        acc.x += v.x; acc.y += v.y; acc.z += v.z; acc.w += v.w;
    }
    float db = g_dinvIn[node];
    float da = g_dinvOut[node];
    float4 bb = ((const float4*)b1)[lane];
    float x0 = fmaxf(fmaf(acc.x, db, bb.x), 0.f) * da;
    float x1 = fmaxf(fmaf(acc.y, db, bb.y), 0.f) * da;
    float x2 = fmaxf(fmaf(acc.z, db, bb.z), 0.f) * da;
    float x3 = fmaxf(fmaf(acc.w, db, bb.w), 0.f) * da;
    unsigned short h0, l0, h1, l1, h2, l2, h3, l3;
    split_bf16(x0, h0, l0); split_bf16(x1, h1, l1);
    split_bf16(x2, h2, l2); split_bf16(x3, h3, l3);
    size_t w = (size_t)node * 64 + lane * 2;
    g_Xhi[w]     = (uint32_t)h0 | ((uint32_t)h1 << 16);
    g_Xhi[w + 1] = (uint32_t)h2 | ((uint32_t)h3 << 16);
    g_Xlo[w]     = (uint32_t)l0 | ((uint32_t)l1 << 16);
    g_Xlo[w + 1] = (uint32_t)l2 | ((uint32_t)l3 << 16);
}

// ---------------------------------------------------------------------------
// Gather-2 (unroll 8) + fused classifier
__global__ void gather2_cls_kernel(const float* __restrict__ b2,
                                   const float* __restrict__ Wc,
                                   const float* __restrict__ bc,
                                   float* __restrict__ out, int nN) {
    int node = blockIdx.x * (blockDim.x >> 5) + (threadIdx.x >> 5);
    int lane = threadIdx.x & 31;
    if (node >= nN) return;
    int b = g_off[node];
    int e = b + g_cntIn[node];
    float4 acc = make_float4(0.f, 0.f, 0.f, 0.f);
    int j = b;
    int e8 = b + ((e - b) & ~7);
    for (; j < e8; j += 8) {
        float4 v[8];
#pragma unroll
        for (int q = 0; q < 8; q++) {
            int s = g_eidx[j + q];
            v[q] = ((const float4*)(g_bufA + (size_t)s * F))[lane];
        }
#pragma unroll
        for (int q = 0; q < 8; q++) {
            acc.x += v[q].x; acc.y += v[q].y; acc.z += v[q].z; acc.w += v[q].w;
        }
    }
    for (; j < e; j++) {
        int s = g_eidx[j];
        float4 v = ((const float4*)(g_bufA + (size_t)s * F))[lane];
        acc.x += v.x; acc.y += v.y; acc.z += v.z; acc.w += v.w;
    }
    float db = g_dinvIn[node];
    float4 bb = ((const float4*)b2)[lane];
    float h[4];
    h[0] = fmaxf(fmaf(acc.x, db, bb.x), 0.f);
    h[1] = fmaxf(fmaf(acc.y, db, bb.y), 0.f);
    h[2] = fmaxf(fmaf(acc.z, db, bb.z), 0.f);
    h[3] = fmaxf(fmaf(acc.w, db, bb.w), 0.f);

    float a0 = 0.f, a1 = 0.f, a2 = 0.f, a3 = 0.f;
    const float4* Wc4 = (const float4*)Wc;
#pragma unroll
    for (int q = 0; q < 4; q++) {
        float4 w = Wc4[lane * 4 + q];
        a0 = fmaf(h[q], w.x, a0);
        a1 = fmaf(h[q], w.y, a1);
        a2 = fmaf(h[q], w.z, a2);
        a3 = fmaf(h[q], w.w, a3);
    }
#pragma unroll
    for (int o = 16; o > 0; o >>= 1) {
        a0 += __shfl_xor_sync(0xffffffffu, a0, o);
        a1 += __shfl_xor_sync(0xffffffffu, a1, o);
        a2 += __shfl_xor_sync(0xffffffffu, a2, o);
        a3 += __shfl_xor_sync(0xffffffffu, a3, o);
    }
    if (lane == 0)
        ((float4*)out)[node] = make_float4(a0 + bc[0], a1 + bc[1], a2 + bc[2], a3 + bc[3]);
}

// ---------------------------------------------------------------------------
extern "C" void kernel_launch(void* const* d_in, const int* in_sizes, int n_in,
                              void* d_out, int out_size) {
    const float* features = (const float*)d_in[0];
    const int*   src      = (const int*)d_in[1];
    const int*   dst      = (const int*)d_in[2];
    const float* W1       = (const float*)d_in[3];
    const float* b1       = (const float*)d_in[4];
    const float* W2       = (const float*)d_in[5];
    const float* b2       = (const float*)d_in[6];
    const float* Wc       = (const float*)d_in[7];
    const float* bc       = (const float*)d_in[8];
    float*       out      = (float*)d_out;

    const int nN  = in_sizes[0] / F;
    const int nE  = in_sizes[1];
    const int nb  = (nN + SCAN_B - 1) / SCAN_B;
    const int nE2 = nE >> 1;
    const int odd = nE & 1;

    unsigned short *w1hi, *w1lo, *w2hi, *w2lo;
    cudaGetSymbolAddress((void**)&w1hi, g_W1hi);
    cudaGetSymbolAddress((void**)&w1lo, g_W1lo);
    cudaGetSymbolAddress((void**)&w2hi, g_W2hi);
    cudaGetSymbolAddress((void**)&w2lo, g_W2lo);

    // Side stream + fork/join events (created on first, uncaptured, call)
    static cudaStream_t s1 = nullptr;
    static cudaEvent_t  eH = nullptr, eG = nullptr;
    if (!s1) {
        cudaStreamCreateWithFlags(&s1, cudaStreamNonBlocking);
        cudaEventCreateWithFlags(&eH, cudaEventDisableTiming);
        cudaEventCreateWithFlags(&eG, cudaEventDisableTiming);
    }

    // s1: weight split is fully independent — start immediately
    wsplit_kernel<<<128, 256, 0, s1>>>(W1, W2);

    // stream0: degrees
    zero_cnt_kernel<<<(nN + 255) / 256, 256>>>(nN);
    hist_kernel<<<(nE2 + 256) / 256, 256>>>((const int2*)src, (const int2*)dst,
                                            nE2, odd, src, dst);
    cudaEventRecord(eH, 0);

    // s1 branch: dinv -> prep -> gemm1  (needs hist only)
    cudaStreamWaitEvent(s1, eH, 0);
    dinv_kernel<<<(nN + 255) / 256, 256, 0, s1>>>(nN);
    prep_kernel<<<(nN * 32 + 255) / 256, 256, 0, s1>>>(features, nN);
    gemm_mma_kernel<<<(nN + 127) / 128, 256, 0, s1>>>(w1hi, w1lo, nN);
    cudaEventRecord(eG, s1);

    // stream0 branch: CSR offsets + fill  (needs hist only)
    scan_block_kernel<<<nb, SCAN_B>>>(nN);
    scan_small_kernel<<<1, 128>>>(nb);
    offsets_kernel<<<(nN + 255) / 256, 256>>>(nN);
    fill_kernel<<<(nE2 + 256) / 256, 256>>>((const int2*)src, (const int2*)dst,
                                            nE2, odd, src, dst);

    // join: gather1 needs fill (stream0) + gemm1/dinv (s1)
    cudaStreamWaitEvent(0, eG, 0);
    gather1_kernel<<<(nN + 7) / 8, 256>>>(b1, nN);

    // layer 2 + fused classifier
    gemm_mma_kernel<<<(nN + 127) / 128, 256>>>(w2hi, w2lo, nN);
    gather2_cls_kernel<<<(nN + 7) / 8, 256>>>(b2, Wc, bc, out, nN);
}